// round 15
// baseline (speedup 1.0000x reference)
#include <cuda_runtime.h>
#include <cstdint>
#include <math.h>

#define TOKENS 32768
#define DMODEL 1024
#define NEXP   64
#define CAP    1024
#define GEMM_BLOCKS 256   /* 32768 / 128 */

// ---------------- scratch (device globals, no allocation) ----------------
__device__ float g_pmax[GEMM_BLOCKS * NEXP];
__device__ float g_gmax[NEXP];
__device__ float g_sum[NEXP];
__device__ float g_lT[(size_t)NEXP * TOKENS];   // logits transposed [e][t], 8.4 MB

__device__ __forceinline__ void cp_async16(void* sdst, const void* gsrc) {
    unsigned s = (unsigned)__cvta_generic_to_shared(sdst);
    asm volatile("cp.async.cg.shared.global [%0], [%1], 16;" :: "r"(s), "l"(gsrc));
}

// ---------------- GEMM: logits = x @ W + b, 2-way block-split-K ----------
// Bitwise contract (== reference, verified R7..R14): per output,
//   acc_lo = ascending-k FMA chain over k in [0,512)
//   acc_hi = ascending-k FMA chain over k in [512,1024)
//   logit  = fl(fl(acc_lo + acc_hi) + bias)
// R12/R14 kernel verbatim (measured 104.2-104.4 us).
#define AS_PAD 36
#define GEMM_SMEM ((2 * 128 * AS_PAD + 2 * 2048 + 1024) * 4)   /* 57344 B */

__global__ __launch_bounds__(256, 2) void gemm_split2_kernel(
    const float* __restrict__ x, const float* __restrict__ W,
    const float* __restrict__ bias_in, float* __restrict__ logits)
{
    extern __shared__ float sm_f[];
    float* Asm = sm_f;
    float* Bsm = sm_f + 2 * 128 * AS_PAD;
    float* red = Bsm + 2 * 2048;

    const int tid = threadIdx.x;
    const int tx = tid & 15;
    const int ty = tid >> 4;
    const int m_base = blockIdx.x * 128;
    const float* xblk = x + (size_t)m_base * DMODEL;

    const int am0 = tid >> 3, ac0 = tid & 7;
    const int bk0 = tid >> 4, bn0 = tid & 15;

    float acc[8][4];
    float accL[8][4];
#pragma unroll
    for (int i = 0; i < 8; i++)
#pragma unroll
        for (int j = 0; j < 4; j++) acc[i][j] = 0.0f;

    {
        float* Ab = Asm; float* Bb = Bsm;
#pragma unroll
        for (int j = 0; j < 4; j++) {
            int m = am0 + j * 32;
            cp_async16(&Ab[m * AS_PAD + ac0 * 4],
                       xblk + (size_t)m * DMODEL + ac0 * 4);
        }
#pragma unroll
        for (int j = 0; j < 2; j++) {
            int kk = bk0 + j * 16;
            cp_async16(&Bb[kk * 64 + bn0 * 4],
                       W + (size_t)kk * NEXP + bn0 * 4);
        }
        asm volatile("cp.async.commit_group;");
    }

#pragma unroll 1
    for (int i = 0; i < 32; i++) {
        if (i < 31) {
            const int kc = (i + 1) * 32;
            float* Ab = Asm + ((i + 1) & 1) * (128 * AS_PAD);
            float* Bb = Bsm + ((i + 1) & 1) * 2048;
#pragma unroll
            for (int j = 0; j < 4; j++) {
                int m = am0 + j * 32;
                cp_async16(&Ab[m * AS_PAD + ac0 * 4],
                           xblk + (size_t)m * DMODEL + kc + ac0 * 4);
            }
#pragma unroll
            for (int j = 0; j < 2; j++) {
                int kk = bk0 + j * 16;
                cp_async16(&Bb[kk * 64 + bn0 * 4],
                           W + (size_t)(kc + kk) * NEXP + bn0 * 4);
            }
            asm volatile("cp.async.commit_group;");
            asm volatile("cp.async.wait_group 1;" ::: "memory");
        } else {
            asm volatile("cp.async.wait_group 0;" ::: "memory");
        }
        __syncthreads();

        const float* Ab = Asm + (i & 1) * (128 * AS_PAD);
        const float* Bb = Bsm + (i & 1) * 2048;
#pragma unroll
        for (int g = 0; g < 8; g++) {
            float4 b0 = *(const float4*)&Bb[(g * 4 + 0) * 64 + tx * 4];
            float4 b1 = *(const float4*)&Bb[(g * 4 + 1) * 64 + tx * 4];
            float4 b2 = *(const float4*)&Bb[(g * 4 + 2) * 64 + tx * 4];
            float4 b3 = *(const float4*)&Bb[(g * 4 + 3) * 64 + tx * 4];
#pragma unroll
            for (int ii = 0; ii < 8; ii++) {
                float4 a = *(const float4*)&Ab[(ty * 8 + ii) * AS_PAD + g * 4];
                acc[ii][0] = __fmaf_rn(a.x, b0.x, acc[ii][0]);
                acc[ii][1] = __fmaf_rn(a.x, b0.y, acc[ii][1]);
                acc[ii][2] = __fmaf_rn(a.x, b0.z, acc[ii][2]);
                acc[ii][3] = __fmaf_rn(a.x, b0.w, acc[ii][3]);
                acc[ii][0] = __fmaf_rn(a.y, b1.x, acc[ii][0]);
                acc[ii][1] = __fmaf_rn(a.y, b1.y, acc[ii][1]);
                acc[ii][2] = __fmaf_rn(a.y, b1.z, acc[ii][2]);
                acc[ii][3] = __fmaf_rn(a.y, b1.w, acc[ii][3]);
                acc[ii][0] = __fmaf_rn(a.z, b2.x, acc[ii][0]);
                acc[ii][1] = __fmaf_rn(a.z, b2.y, acc[ii][1]);
                acc[ii][2] = __fmaf_rn(a.z, b2.z, acc[ii][2]);
                acc[ii][3] = __fmaf_rn(a.z, b2.w, acc[ii][3]);
                acc[ii][0] = __fmaf_rn(a.w, b3.x, acc[ii][0]);
                acc[ii][1] = __fmaf_rn(a.w, b3.y, acc[ii][1]);
                acc[ii][2] = __fmaf_rn(a.w, b3.z, acc[ii][2]);
                acc[ii][3] = __fmaf_rn(a.w, b3.w, acc[ii][3]);
            }
        }
        __syncthreads();

        if (i == 15) {
#pragma unroll
            for (int ii = 0; ii < 8; ii++)
#pragma unroll
                for (int j = 0; j < 4; j++) { accL[ii][j] = acc[ii][j]; acc[ii][j] = 0.0f; }
        }
    }

    float4 bb = *(const float4*)(bias_in + tx * 4);
    float bias[4] = {bb.x, bb.y, bb.z, bb.w};
    float fin[8][4];
#pragma unroll
    for (int i = 0; i < 8; i++)
#pragma unroll
        for (int j = 0; j < 4; j++)
            fin[i][j] = __fadd_rn(__fadd_rn(accL[i][j], acc[i][j]), bias[j]);

    float cmax[4] = {-3.4e38f, -3.4e38f, -3.4e38f, -3.4e38f};
#pragma unroll
    for (int i = 0; i < 8; i++) {
        float4 o = make_float4(fin[i][0], fin[i][1], fin[i][2], fin[i][3]);
        *(float4*)(logits + (size_t)(m_base + ty * 8 + i) * NEXP + tx * 4) = o;
        cmax[0] = fmaxf(cmax[0], o.x); cmax[1] = fmaxf(cmax[1], o.y);
        cmax[2] = fmaxf(cmax[2], o.z); cmax[3] = fmaxf(cmax[3], o.w);
    }
#pragma unroll
    for (int j = 0; j < 4; j++) {
        float4 t0 = make_float4(fin[0][j], fin[1][j], fin[2][j], fin[3][j]);
        float4 t1 = make_float4(fin[4][j], fin[5][j], fin[6][j], fin[7][j]);
        float* base = g_lT + (size_t)(tx * 4 + j) * TOKENS + m_base + ty * 8;
        *(float4*)(base + 0) = t0;
        *(float4*)(base + 4) = t1;
    }
#pragma unroll
    for (int j = 0; j < 4; j++) red[ty * 64 + tx * 4 + j] = cmax[j];
    __syncthreads();
    if (tid < 64) {
        float m = red[tid];
#pragma unroll
        for (int w = 1; w < 16; w++) m = fmaxf(m, red[w * 64 + tid]);
        g_pmax[(size_t)blockIdx.x * NEXP + tid] = m;
    }
}

// ---------------- fused: M + S + exact stable top-1024 per expert ---------
__device__ __forceinline__ unsigned mono_fwd(float f) {
    unsigned u = __float_as_uint(f);
    return (u & 0x80000000u) ? ~u : (u | 0x80000000u);
}
__device__ __forceinline__ float mono_inv(unsigned m) {
    unsigned u = (m & 0x80000000u) ? (m ^ 0x80000000u) : ~m;
    return __uint_as_float(u);
}

// warp-aggregated histogram add (counts identical to per-lane atomics)
__device__ __forceinline__ void hist_add(unsigned* hist, unsigned bin, bool valid) {
    unsigned eff = valid ? bin : 0xFFFFFFFFu;
    unsigned mask = __match_any_sync(0xFFFFFFFFu, eff);
    unsigned lane = threadIdx.x & 31;
    if (valid && ((__ffs(mask) - 1) == lane))
        atomicAdd(&hist[bin], (unsigned)__popc(mask));
}

// warp-aggregated counter push: returns slot (valid lanes only)
__device__ __forceinline__ unsigned warp_push(unsigned* ctr, bool pred, unsigned lane) {
    unsigned mask = __ballot_sync(0xFFFFFFFFu, pred);
    unsigned slot = 0xFFFFFFFFu;
    if (pred) {
        unsigned ldr = __ffs(mask) - 1;
        unsigned base;
        if (lane == ldr) base = atomicAdd(ctr, (unsigned)__popc(mask));
        base = __shfl_sync(mask, base, ldr);
        slot = base + (unsigned)__popc(mask & ((1u << lane) - 1u));
    }
    return slot;
}

// smem layout offsets (bytes)
#define OFF_VALS  0
#define OFF_CAND  131072
#define OFF_DRED  (131072 + 8192)
#define OFF_HIST  (131072 + 16384)
#define OFF_WTMP  (131072 + 16384 + 8192)
#define OFF_FRED  (131072 + 16384 + 8192 + 128)
#define OFF_CBUF  (131072 + 16384 + 8192 + 128 + 1024)
#define CBUF_N    8192
#define TOPK_SMEM (OFF_CBUF + CBUF_N * 8)

// descending bucket select over 2048 bins: first bin from TOP with cum >= k.
__device__ __forceinline__ void block_select2048(
    unsigned* hist, unsigned* wtmp, int k, int tid,
    volatile int* s_sel, volatile int* s_rem)
{
    const int lane = tid & 31, wid = tid >> 5;
    unsigned a = hist[2047 - 2 * tid];
    unsigned b = hist[2047 - (2 * tid + 1)];
    unsigned s = a + b, v = s;
#pragma unroll
    for (int o = 1; o < 32; o <<= 1) {
        unsigned n = __shfl_up_sync(0xffffffffu, v, o);
        if (lane >= o) v += n;
    }
    if (lane == 31) wtmp[wid] = v;
    __syncthreads();
    if (wid == 0) {
        unsigned w = wtmp[lane], vv = w;
#pragma unroll
        for (int o = 1; o < 32; o <<= 1) {
            unsigned n = __shfl_up_sync(0xffffffffu, vv, o);
            if (lane >= o) vv += n;
        }
        wtmp[lane] = vv - w;
    }
    __syncthreads();
    unsigned ex = wtmp[wid] + (v - s);
    unsigned uk = (unsigned)k;
    if (ex < uk && uk <= ex + a) { *s_sel = 2047 - 2 * tid; *s_rem = (int)(uk - ex); }
    unsigned e1 = ex + a;
    if (e1 < uk && uk <= e1 + b) { *s_sel = 2046 - 2 * tid; *s_rem = (int)(uk - e1); }
    __syncthreads();
}

__global__ __launch_bounds__(1024) void topk_kernel(
    float* __restrict__ out_val, float* __restrict__ out_idx)
{
    extern __shared__ unsigned char sm_raw[];
    float*              uval = (float*)(sm_raw + OFF_VALS);
    unsigned*           vals = (unsigned*)(sm_raw + OFF_VALS);
    unsigned long long* cand = (unsigned long long*)(sm_raw + OFF_CAND);
    double*             dred = (double*)(sm_raw + OFF_DRED);
    unsigned*           hist = (unsigned*)(sm_raw + OFF_HIST);
    int*                eqbuf = (int*)(sm_raw + OFF_HIST);      // aliases hist
    unsigned*           wtmp = (unsigned*)(sm_raw + OFF_WTMP);
    float*              fred = (float*)(sm_raw + OFF_FRED);
    unsigned long long* cbuf = (unsigned long long*)(sm_raw + OFF_CBUF); // (v,~i)

    __shared__ volatile int s_sel;
    __shared__ volatile int s_k;
    __shared__ unsigned     s_cnt;
    __shared__ unsigned     s_eqc;
    __shared__ unsigned     s_cb;
    __shared__ float        s_S;

    const int tid = threadIdx.x;
    const int e   = blockIdx.x;
    const unsigned lane = tid & 31;

    // ---- M = exact column max from per-tile maxes ----
    if (tid < GEMM_BLOCKS) fred[tid] = g_pmax[(size_t)tid * NEXP + e];
    __syncthreads();
    for (int st = GEMM_BLOCKS / 2; st > 0; st >>= 1) {
        if (tid < st) fred[tid] = fmaxf(fred[tid], fred[tid + st]);
        __syncthreads();
    }
    const float M = fred[0];
    if (tid == 0) g_gmax[e] = M;

    const float4* col = (const float4*)(g_lT + (size_t)e * TOKENS);

    // ---- u = expf(l - M); S = fl32(f64 sum, 4 lanes + tree) (== R13/R14) ----
    double s0 = 0.0, s1 = 0.0, s2 = 0.0, s3 = 0.0;
    for (int i = tid; i < TOKENS / 4; i += 1024) {
        float4 l = col[i];
        float u0 = expf(__fsub_rn(l.x, M));
        float u1 = expf(__fsub_rn(l.y, M));
        float u2 = expf(__fsub_rn(l.z, M));
        float u3 = expf(__fsub_rn(l.w, M));
        uval[4 * i + 0] = u0; uval[4 * i + 1] = u1;
        uval[4 * i + 2] = u2; uval[4 * i + 3] = u3;
        s0 += (double)u0; s1 += (double)u1; s2 += (double)u2; s3 += (double)u3;
    }
    dred[tid] = (s0 + s1) + (s2 + s3);
    __syncthreads();
    for (int st = 512; st > 0; st >>= 1) {
        if (tid < st) dred[tid] += dred[tid + st];
        __syncthreads();
    }
    if (tid == 0) { s_S = (float)dred[0]; g_sum[e] = s_S; }
    hist[tid] = 0; hist[tid + 1024] = 0;
    __syncthreads();
    const float S = s_S;

    // ---- keys = mono(fdiv(u, S)) in place, fused pass-1 hist (aggregated) ----
    for (int i = tid; i < TOKENS; i += 1024) {
        unsigned v = mono_fwd(__fdiv_rn(uval[i], S));
        vals[i] = v;
        hist_add(hist, v >> 21, true);
    }
    __syncthreads();

    // ---- pass-1 select ----
    block_select2048(hist, wtmp, CAP, tid, &s_sel, &s_k);
    const unsigned pre11 = (unsigned)s_sel;
    int krem = s_k;
    __syncthreads();

    // ---- SINGLE full scan: bin>pre11 -> cand, bin==pre11 -> cbuf (aggregated)
    if (tid == 0) { s_cnt = 0; s_cb = 0; }
    __syncthreads();
    for (int i = tid; i < TOKENS; i += 1024) {
        unsigned v = vals[i];
        unsigned bin = v >> 21;
        unsigned long long kv = ((unsigned long long)v << 32)
                                | (unsigned)(~(unsigned)i);
        unsigned sg = warp_push(&s_cnt, bin > pre11, lane);
        if (sg != 0xFFFFFFFFu) cand[sg] = kv;
        unsigned sb = warp_push(&s_cb, bin == pre11, lane);
        if (sb != 0xFFFFFFFFu && sb < CBUF_N) cbuf[sb] = kv;
    }
    __syncthreads();
    const bool usec = (s_cb <= CBUF_N);
    const int  ncb  = usec ? (int)s_cb : 0;
    const int  ncb_r = (ncb + 1023) & ~1023;

    // ---- pass 2: bins = (v>>10)&0x7FF over survivors (aggregated) ----
    hist[tid] = 0; hist[tid + 1024] = 0;
    __syncthreads();
    if (usec) {
        for (int l = tid; l < ncb_r; l += 1024) {
            bool inb = l < ncb;
            unsigned bin = inb ? (((unsigned)(cbuf[l] >> 42)) & 0x7FFu) : 0u;
            hist_add(hist, bin, inb);
        }
    } else {
        for (int i = tid; i < TOKENS; i += 1024) {
            unsigned v = vals[i];
            hist_add(hist, (v >> 10) & 0x7FFu, (v >> 21) == pre11);
        }
    }
    __syncthreads();
    block_select2048(hist, wtmp, krem, tid, &s_sel, &s_k);
    const unsigned pre22 = (pre11 << 11) | (unsigned)s_sel;
    krem = s_k;
    __syncthreads();

    // ---- pass 3: bins = v & 0x3FF over survivors (aggregated) ----
    hist[tid] = 0; hist[tid + 1024] = 0;
    __syncthreads();
    if (usec) {
        for (int l = tid; l < ncb_r; l += 1024) {
            bool inb = l < ncb;
            unsigned v = inb ? (unsigned)(cbuf[l] >> 32) : 0u;
            hist_add(hist, v & 0x3FFu, inb && ((v >> 10) == pre22));
        }
    } else {
        for (int i = tid; i < TOKENS; i += 1024) {
            unsigned v = vals[i];
            hist_add(hist, v & 0x3FFu, (v >> 10) == pre22);
        }
    }
    __syncthreads();
    block_select2048(hist, wtmp, krem, tid, &s_sel, &s_k);
    const unsigned th = (pre22 << 10) | (unsigned)s_sel;
    const int r = s_k;
    __syncthreads();

    // ---- collect from survivors: v > th -> cand; v == th -> eqbuf ----
    if (tid == 0) s_eqc = 0;
    __syncthreads();
    if (usec) {
        for (int l = tid; l < ncb_r; l += 1024) {
            bool inb = l < ncb;
            unsigned long long kv = inb ? cbuf[l] : 0ull;
            unsigned v = (unsigned)(kv >> 32);
            unsigned sg = warp_push(&s_cnt, inb && v > th, lane);
            if (sg != 0xFFFFFFFFu) cand[sg] = kv;
            unsigned se = warp_push(&s_eqc, inb && v == th, lane);
            if (se != 0xFFFFFFFFu && se < 2048u)
                eqbuf[se] = (int)(~(unsigned)(kv & 0xffffffffu));
        }
    } else {
        for (int i = tid; i < TOKENS; i += 1024) {
            unsigned v = vals[i];
            unsigned long long kv = ((unsigned long long)v << 32)
                                    | (unsigned)(~(unsigned)i);
            unsigned sg = warp_push(&s_cnt, v > th && (v >> 21) == pre11, lane);
            if (sg != 0xFFFFFFFFu) cand[sg] = kv;
            unsigned se = warp_push(&s_eqc, v == th, lane);
            if (se != 0xFFFFFFFFu && se < 2048u) eqbuf[se] = i;
        }
    }
    __syncthreads();
    const int cnt_eq = (int)s_eqc;
    const int eqbase = CAP - r;

    if (cnt_eq == r) {
        for (int l = tid; l < r; l += 1024)
            cand[eqbase + l] =
                ((unsigned long long)th << 32) | (unsigned)(~(unsigned)eqbuf[l]);
    } else if (cnt_eq <= 2048) {
        for (int l = tid; l < cnt_eq; l += 1024) {
            int idx = eqbuf[l];
            int rank = 0;
            for (int m = 0; m < cnt_eq; m++) rank += (eqbuf[m] < idx) ? 1 : 0;
            if (rank < r)
                cand[eqbase + rank] =
                    ((unsigned long long)th << 32) | (unsigned)(~(unsigned)idx);
        }
    } else {
        for (int i = tid; i < TOKENS; i += 1024) {
            if (vals[i] == th) {
                int rank = 0;
                for (int j = 0; j < i; j++) rank += (vals[j] == th) ? 1 : 0;
                if (rank < r)
                    cand[eqbase + rank] =
                        ((unsigned long long)th << 32) | (unsigned)(~(unsigned)i);
            }
        }
    }
    __syncthreads();

    // ---- hybrid bitonic sort: 1024 keys, DESC (val desc, idx asc) ----
    unsigned long long key = cand[tid];
#pragma unroll 1
    for (unsigned kk = 2; kk <= 1024; kk <<= 1) {
        unsigned j = kk >> 1;
        for (; j >= 32; j >>= 1) {
            cand[tid] = key;
            __syncthreads();
            unsigned long long p = cand[tid ^ j];
            bool up = ((tid & kk) == 0);
            bool lowr = ((tid & j) == 0);
            bool takeMax = (up == lowr);
            key = takeMax ? (key > p ? key : p) : (key > p ? p : key);
            __syncthreads();
        }
        for (; j >= 1; j >>= 1) {
            unsigned long long p = __shfl_xor_sync(0xffffffffu, key, j);
            bool up = ((tid & kk) == 0);
            bool lowr = ((tid & j) == 0);
            bool takeMax = (up == lowr);
            key = takeMax ? (key > p ? key : p) : (key > p ? p : key);
        }
    }

    unsigned m   = (unsigned)(key >> 32);
    unsigned idx = ~(unsigned)(key & 0xffffffffu);
    out_val[(size_t)e * CAP + tid] = mono_inv(m);
    out_idx[(size_t)e * CAP + tid] = (float)idx;
}

// ---------------- probs = fl( expf(l - M) / S ), vectorized x4 ------------
__global__ __launch_bounds__(256) void probs_kernel(
    const float* __restrict__ logits, float* __restrict__ probs)
{
    __shared__ float sM[64], sS[64];
    if (threadIdx.x < 64) {
        sM[threadIdx.x] = g_gmax[threadIdx.x];
        sS[threadIdx.x] = g_sum[threadIdx.x];
    }
    __syncthreads();
    int i4 = (blockIdx.x * 256 + threadIdx.x) * 4;
    float4 l = *(const float4*)(logits + i4);
    int e0 = i4 & 63;
    float4 p;
    p.x = __fdiv_rn(expf(__fsub_rn(l.x, sM[e0 + 0])), sS[e0 + 0]);
    p.y = __fdiv_rn(expf(__fsub_rn(l.y, sM[e0 + 1])), sS[e0 + 1]);
    p.z = __fdiv_rn(expf(__fsub_rn(l.z, sM[e0 + 2])), sS[e0 + 2]);
    p.w = __fdiv_rn(expf(__fsub_rn(l.w, sM[e0 + 3])), sS[e0 + 3]);
    *(float4*)(probs + i4) = p;
}

// ---------------- launch ----------------
extern "C" void kernel_launch(void* const* d_in, const int* in_sizes, int n_in,
                              void* d_out, int out_size)
{
    const float* x = (const float*)d_in[0];
    const float* W = (const float*)d_in[1];
    const float* b = (const float*)d_in[2];
    (void)in_sizes; (void)n_in; (void)out_size;

    float* out    = (float*)d_out;
    float* logits = out;                                  // 32768*64
    float* probs  = out + (size_t)TOKENS * NEXP;          // 32768*64
    float* ep     = out + 2 * (size_t)TOKENS * NEXP;      // 64*1024
    float* ei     = ep  + (size_t)NEXP * CAP;             // 64*1024

    cudaFuncSetAttribute(gemm_split2_kernel,
                         cudaFuncAttributeMaxDynamicSharedMemorySize, GEMM_SMEM);
    cudaFuncSetAttribute(topk_kernel,
                         cudaFuncAttributeMaxDynamicSharedMemorySize, TOPK_SMEM);

    gemm_split2_kernel<<<GEMM_BLOCKS, 256, GEMM_SMEM>>>(x, W, b, logits);
    topk_kernel<<<NEXP, 1024, TOPK_SMEM>>>(ep, ei);
    probs_kernel<<<(TOKENS * NEXP) / 1024, 256>>>(logits, probs);
}

// round 16
// speedup vs baseline: 1.1068x; 1.1068x over previous
#include <cuda_runtime.h>
#include <cstdint>
#include <math.h>

#define TOKENS 32768
#define DMODEL 1024
#define NEXP   64
#define CAP    1024
#define GEMM_BLOCKS 256   /* 32768 / 128 */

// ---------------- scratch (device globals, no allocation) ----------------
__device__ float g_pmax[GEMM_BLOCKS * NEXP];
__device__ float g_gmax[NEXP];
__device__ float g_sum[NEXP];
__device__ float g_lT[(size_t)NEXP * TOKENS];      // logits transposed [e][t]
__device__ double g_dred[NEXP * 1024];             // per-(e,vthread) f64 partials
__device__ unsigned g_kT[(size_t)NEXP * TOKENS];   // prob bit-keys [e][t]

__device__ __forceinline__ void cp_async16(void* sdst, const void* gsrc) {
    unsigned s = (unsigned)__cvta_generic_to_shared(sdst);
    asm volatile("cp.async.cg.shared.global [%0], [%1], 16;" :: "r"(s), "l"(gsrc));
}

// ---------------- GEMM: logits = x @ W + b, 2-way block-split-K ----------
// Bitwise contract (== reference, verified R7..R15): per output,
//   acc_lo = ascending-k FMA chain over k in [0,512)
//   acc_hi = ascending-k FMA chain over k in [512,1024)
//   logit  = fl(fl(acc_lo + acc_hi) + bias)
// R12/R14 kernel verbatim (measured 104.2-104.8 us).
#define AS_PAD 36
#define GEMM_SMEM ((2 * 128 * AS_PAD + 2 * 2048 + 1024) * 4)   /* 57344 B */

__global__ __launch_bounds__(256, 2) void gemm_split2_kernel(
    const float* __restrict__ x, const float* __restrict__ W,
    const float* __restrict__ bias_in, float* __restrict__ logits)
{
    extern __shared__ float sm_f[];
    float* Asm = sm_f;
    float* Bsm = sm_f + 2 * 128 * AS_PAD;
    float* red = Bsm + 2 * 2048;

    const int tid = threadIdx.x;
    const int tx = tid & 15;
    const int ty = tid >> 4;
    const int m_base = blockIdx.x * 128;
    const float* xblk = x + (size_t)m_base * DMODEL;

    const int am0 = tid >> 3, ac0 = tid & 7;
    const int bk0 = tid >> 4, bn0 = tid & 15;

    float acc[8][4];
    float accL[8][4];
#pragma unroll
    for (int i = 0; i < 8; i++)
#pragma unroll
        for (int j = 0; j < 4; j++) acc[i][j] = 0.0f;

    {
        float* Ab = Asm; float* Bb = Bsm;
#pragma unroll
        for (int j = 0; j < 4; j++) {
            int m = am0 + j * 32;
            cp_async16(&Ab[m * AS_PAD + ac0 * 4],
                       xblk + (size_t)m * DMODEL + ac0 * 4);
        }
#pragma unroll
        for (int j = 0; j < 2; j++) {
            int kk = bk0 + j * 16;
            cp_async16(&Bb[kk * 64 + bn0 * 4],
                       W + (size_t)kk * NEXP + bn0 * 4);
        }
        asm volatile("cp.async.commit_group;");
    }

#pragma unroll 1
    for (int i = 0; i < 32; i++) {
        if (i < 31) {
            const int kc = (i + 1) * 32;
            float* Ab = Asm + ((i + 1) & 1) * (128 * AS_PAD);
            float* Bb = Bsm + ((i + 1) & 1) * 2048;
#pragma unroll
            for (int j = 0; j < 4; j++) {
                int m = am0 + j * 32;
                cp_async16(&Ab[m * AS_PAD + ac0 * 4],
                           xblk + (size_t)m * DMODEL + kc + ac0 * 4);
            }
#pragma unroll
            for (int j = 0; j < 2; j++) {
                int kk = bk0 + j * 16;
                cp_async16(&Bb[kk * 64 + bn0 * 4],
                           W + (size_t)(kc + kk) * NEXP + bn0 * 4);
            }
            asm volatile("cp.async.commit_group;");
            asm volatile("cp.async.wait_group 1;" ::: "memory");
        } else {
            asm volatile("cp.async.wait_group 0;" ::: "memory");
        }
        __syncthreads();

        const float* Ab = Asm + (i & 1) * (128 * AS_PAD);
        const float* Bb = Bsm + (i & 1) * 2048;
#pragma unroll
        for (int g = 0; g < 8; g++) {
            float4 b0 = *(const float4*)&Bb[(g * 4 + 0) * 64 + tx * 4];
            float4 b1 = *(const float4*)&Bb[(g * 4 + 1) * 64 + tx * 4];
            float4 b2 = *(const float4*)&Bb[(g * 4 + 2) * 64 + tx * 4];
            float4 b3 = *(const float4*)&Bb[(g * 4 + 3) * 64 + tx * 4];
#pragma unroll
            for (int ii = 0; ii < 8; ii++) {
                float4 a = *(const float4*)&Ab[(ty * 8 + ii) * AS_PAD + g * 4];
                acc[ii][0] = __fmaf_rn(a.x, b0.x, acc[ii][0]);
                acc[ii][1] = __fmaf_rn(a.x, b0.y, acc[ii][1]);
                acc[ii][2] = __fmaf_rn(a.x, b0.z, acc[ii][2]);
                acc[ii][3] = __fmaf_rn(a.x, b0.w, acc[ii][3]);
                acc[ii][0] = __fmaf_rn(a.y, b1.x, acc[ii][0]);
                acc[ii][1] = __fmaf_rn(a.y, b1.y, acc[ii][1]);
                acc[ii][2] = __fmaf_rn(a.y, b1.z, acc[ii][2]);
                acc[ii][3] = __fmaf_rn(a.y, b1.w, acc[ii][3]);
                acc[ii][0] = __fmaf_rn(a.z, b2.x, acc[ii][0]);
                acc[ii][1] = __fmaf_rn(a.z, b2.y, acc[ii][1]);
                acc[ii][2] = __fmaf_rn(a.z, b2.z, acc[ii][2]);
                acc[ii][3] = __fmaf_rn(a.z, b2.w, acc[ii][3]);
                acc[ii][0] = __fmaf_rn(a.w, b3.x, acc[ii][0]);
                acc[ii][1] = __fmaf_rn(a.w, b3.y, acc[ii][1]);
                acc[ii][2] = __fmaf_rn(a.w, b3.z, acc[ii][2]);
                acc[ii][3] = __fmaf_rn(a.w, b3.w, acc[ii][3]);
            }
        }
        __syncthreads();

        if (i == 15) {
#pragma unroll
            for (int ii = 0; ii < 8; ii++)
#pragma unroll
                for (int j = 0; j < 4; j++) { accL[ii][j] = acc[ii][j]; acc[ii][j] = 0.0f; }
        }
    }

    float4 bb = *(const float4*)(bias_in + tx * 4);
    float bias[4] = {bb.x, bb.y, bb.z, bb.w};
    float fin[8][4];
#pragma unroll
    for (int i = 0; i < 8; i++)
#pragma unroll
        for (int j = 0; j < 4; j++)
            fin[i][j] = __fadd_rn(__fadd_rn(accL[i][j], acc[i][j]), bias[j]);

    float cmax[4] = {-3.4e38f, -3.4e38f, -3.4e38f, -3.4e38f};
#pragma unroll
    for (int i = 0; i < 8; i++) {
        float4 o = make_float4(fin[i][0], fin[i][1], fin[i][2], fin[i][3]);
        *(float4*)(logits + (size_t)(m_base + ty * 8 + i) * NEXP + tx * 4) = o;
        cmax[0] = fmaxf(cmax[0], o.x); cmax[1] = fmaxf(cmax[1], o.y);
        cmax[2] = fmaxf(cmax[2], o.z); cmax[3] = fmaxf(cmax[3], o.w);
    }
#pragma unroll
    for (int j = 0; j < 4; j++) {
        float4 t0 = make_float4(fin[0][j], fin[1][j], fin[2][j], fin[3][j]);
        float4 t1 = make_float4(fin[4][j], fin[5][j], fin[6][j], fin[7][j]);
        float* base = g_lT + (size_t)(tx * 4 + j) * TOKENS + m_base + ty * 8;
        *(float4*)(base + 0) = t0;
        *(float4*)(base + 4) = t1;
    }
#pragma unroll
    for (int j = 0; j < 4; j++) red[ty * 64 + tx * 4 + j] = cmax[j];
    __syncthreads();
    if (tid < 64) {
        float m = red[tid];
#pragma unroll
        for (int w = 1; w < 16; w++) m = fmaxf(m, red[w * 64 + tid]);
        g_pmax[(size_t)blockIdx.x * NEXP + tid] = m;
    }
}

// ---------------- M per expert (same fmax tree as before) -----------------
__global__ __launch_bounds__(256) void max_kernel()
{
    __shared__ float fred[256];
    const int e = blockIdx.x, tid = threadIdx.x;
    fred[tid] = g_pmax[(size_t)tid * NEXP + e];
    __syncthreads();
    for (int st = 128; st > 0; st >>= 1) {
        if (tid < st) fred[tid] = fmaxf(fred[tid], fred[tid + st]);
        __syncthreads();
    }
    if (tid == 0) g_gmax[e] = fred[0];
}

// ---------------- full-chip: per-(e,vthread) f64 partial sums -------------
// Thread (e, vt) computes EXACTLY the old topk per-thread partial:
//   s_j over i = vt, vt+1024, ... (ascending), dred = (s0+s1)+(s2+s3)
__global__ __launch_bounds__(256) void sumexp_kernel()
{
    const int g = blockIdx.x * 256 + threadIdx.x;    // 0..65535
    const int e = g >> 10, vt = g & 1023;
    const float M = g_gmax[e];
    const float4* col = (const float4*)(g_lT + (size_t)e * TOKENS);
    double s0 = 0.0, s1 = 0.0, s2 = 0.0, s3 = 0.0;
#pragma unroll
    for (int i = vt; i < TOKENS / 4; i += 1024) {
        float4 l = col[i];
        s0 += (double)expf(__fsub_rn(l.x, M));
        s1 += (double)expf(__fsub_rn(l.y, M));
        s2 += (double)expf(__fsub_rn(l.z, M));
        s3 += (double)expf(__fsub_rn(l.w, M));
    }
    g_dred[g] = (s0 + s1) + (s2 + s3);
}

// ---------------- S = fl32(tree over 1024 partials) (same order) ----------
__global__ __launch_bounds__(1024) void sumred_kernel()
{
    __shared__ double dred[1024];
    const int e = blockIdx.x, tid = threadIdx.x;
    dred[tid] = g_dred[e * 1024 + tid];
    __syncthreads();
    for (int st = 512; st > 0; st >>= 1) {
        if (tid < st) dred[tid] += dred[tid + st];
        __syncthreads();
    }
    if (tid == 0) g_sum[e] = (float)dred[0];
}

// ---------------- full-chip: keys = mono(fdiv(expf(l-M), S)) --------------
__device__ __forceinline__ unsigned mono_fwd(float f) {
    unsigned u = __float_as_uint(f);
    return (u & 0x80000000u) ? ~u : (u | 0x80000000u);
}
__device__ __forceinline__ float mono_inv(unsigned m) {
    unsigned u = (m & 0x80000000u) ? (m ^ 0x80000000u) : ~m;
    return __uint_as_float(u);
}

__global__ __launch_bounds__(256) void keys_kernel()
{
    const int NF4 = TOKENS * NEXP / 4;               // 524288 float4s
    for (int f = blockIdx.x * 256 + threadIdx.x; f < NF4; f += gridDim.x * 256) {
        const int e = f >> 13;                       // 8192 float4 per column
        const float M = g_gmax[e];
        const float S = g_sum[e];
        float4 l = ((const float4*)g_lT)[f];
        uint4 k;
        k.x = mono_fwd(__fdiv_rn(expf(__fsub_rn(l.x, M)), S));
        k.y = mono_fwd(__fdiv_rn(expf(__fsub_rn(l.y, M)), S));
        k.z = mono_fwd(__fdiv_rn(expf(__fsub_rn(l.z, M)), S));
        k.w = mono_fwd(__fdiv_rn(expf(__fsub_rn(l.w, M)), S));
        ((uint4*)g_kT)[f] = k;
    }
}

// ---------------- topk: select + sort only (no transcendentals) -----------
// smem layout offsets (bytes)
#define OFF_VALS  0
#define OFF_CAND  131072
#define OFF_HIST  (131072 + 8192)
#define OFF_WTMP  (131072 + 16384)
#define OFF_CBUF  (131072 + 16384 + 128)
#define CBUF_N    8192
#define TOPK_SMEM (OFF_CBUF + CBUF_N * 8)   /* 213120 B */

// descending bucket select over 2048 bins: first bin from TOP with cum >= k.
__device__ __forceinline__ void block_select2048(
    unsigned* hist, unsigned* wtmp, int k, int tid,
    volatile int* s_sel, volatile int* s_rem)
{
    const int lane = tid & 31, wid = tid >> 5;
    unsigned a = hist[2047 - 2 * tid];
    unsigned b = hist[2047 - (2 * tid + 1)];
    unsigned s = a + b, v = s;
#pragma unroll
    for (int o = 1; o < 32; o <<= 1) {
        unsigned n = __shfl_up_sync(0xffffffffu, v, o);
        if (lane >= o) v += n;
    }
    if (lane == 31) wtmp[wid] = v;
    __syncthreads();
    if (wid == 0) {
        unsigned w = wtmp[lane], vv = w;
#pragma unroll
        for (int o = 1; o < 32; o <<= 1) {
            unsigned n = __shfl_up_sync(0xffffffffu, vv, o);
            if (lane >= o) vv += n;
        }
        wtmp[lane] = vv - w;
    }
    __syncthreads();
    unsigned ex = wtmp[wid] + (v - s);
    unsigned uk = (unsigned)k;
    if (ex < uk && uk <= ex + a) { *s_sel = 2047 - 2 * tid; *s_rem = (int)(uk - ex); }
    unsigned e1 = ex + a;
    if (e1 < uk && uk <= e1 + b) { *s_sel = 2046 - 2 * tid; *s_rem = (int)(uk - e1); }
    __syncthreads();
}

__global__ __launch_bounds__(1024) void topk_kernel(
    float* __restrict__ out_val, float* __restrict__ out_idx)
{
    extern __shared__ unsigned char sm_raw[];
    unsigned*           vals = (unsigned*)(sm_raw + OFF_VALS);
    unsigned long long* cand = (unsigned long long*)(sm_raw + OFF_CAND);
    unsigned*           hist = (unsigned*)(sm_raw + OFF_HIST);
    int*                eqbuf = (int*)(sm_raw + OFF_HIST);      // aliases hist
    unsigned*           wtmp = (unsigned*)(sm_raw + OFF_WTMP);
    unsigned long long* cbuf = (unsigned long long*)(sm_raw + OFF_CBUF); // (v,~i)

    __shared__ volatile int s_sel;
    __shared__ volatile int s_k;
    __shared__ unsigned     s_cnt;
    __shared__ unsigned     s_eqc;
    __shared__ unsigned     s_cb;

    const int tid = threadIdx.x;
    const int e   = blockIdx.x;

    // ---- load keys + fused pass-1 histogram (plain atomics) ----
    hist[tid] = 0; hist[tid + 1024] = 0;
    __syncthreads();
    const uint4* colk = (const uint4*)(g_kT + (size_t)e * TOKENS);
    for (int i = tid; i < TOKENS / 4; i += 1024) {
        uint4 kv = colk[i];
        ((uint4*)vals)[i] = kv;
        atomicAdd(&hist[kv.x >> 21], 1u);
        atomicAdd(&hist[kv.y >> 21], 1u);
        atomicAdd(&hist[kv.z >> 21], 1u);
        atomicAdd(&hist[kv.w >> 21], 1u);
    }
    __syncthreads();

    // ---- pass-1 select ----
    block_select2048(hist, wtmp, CAP, tid, &s_sel, &s_k);
    const unsigned pre11 = (unsigned)s_sel;
    int krem = s_k;
    __syncthreads();

    // ---- SINGLE full scan: bin>pre11 -> cand, bin==pre11 -> cbuf ----
    if (tid == 0) { s_cnt = 0; s_cb = 0; }
    __syncthreads();
    for (int i = tid; i < TOKENS; i += 1024) {
        unsigned v = vals[i];
        unsigned bin = v >> 21;
        if (bin > pre11) {
            unsigned p = atomicAdd(&s_cnt, 1u);
            cand[p] = ((unsigned long long)v << 32) | (unsigned)(~(unsigned)i);
        } else if (bin == pre11) {
            unsigned p = atomicAdd(&s_cb, 1u);
            if (p < CBUF_N) cbuf[p] = ((unsigned long long)v << 32)
                                      | (unsigned)(~(unsigned)i);
        }
    }
    __syncthreads();
    const bool usec = (s_cb <= CBUF_N);
    const int  ncb  = usec ? (int)s_cb : 0;

    // ---- pass 2: bins = (v>>10)&0x7FF over survivors ----
    hist[tid] = 0; hist[tid + 1024] = 0;
    __syncthreads();
    if (usec) {
        for (int l = tid; l < ncb; l += 1024)
            atomicAdd(&hist[((unsigned)(cbuf[l] >> 42)) & 0x7FFu], 1u);
    } else {
        for (int i = tid; i < TOKENS; i += 1024) {
            unsigned v = vals[i];
            if ((v >> 21) == pre11) atomicAdd(&hist[(v >> 10) & 0x7FFu], 1u);
        }
    }
    __syncthreads();
    block_select2048(hist, wtmp, krem, tid, &s_sel, &s_k);
    const unsigned pre22 = (pre11 << 11) | (unsigned)s_sel;
    krem = s_k;
    __syncthreads();

    // ---- pass 3: bins = v & 0x3FF over survivors ----
    hist[tid] = 0; hist[tid + 1024] = 0;
    __syncthreads();
    if (usec) {
        for (int l = tid; l < ncb; l += 1024) {
            unsigned v = (unsigned)(cbuf[l] >> 32);
            if ((v >> 10) == pre22) atomicAdd(&hist[v & 0x3FFu], 1u);
        }
    } else {
        for (int i = tid; i < TOKENS; i += 1024) {
            unsigned v = vals[i];
            if ((v >> 10) == pre22) atomicAdd(&hist[v & 0x3FFu], 1u);
        }
    }
    __syncthreads();
    block_select2048(hist, wtmp, krem, tid, &s_sel, &s_k);
    const unsigned th = (pre22 << 10) | (unsigned)s_sel;
    const int r = s_k;
    __syncthreads();

    // ---- collect from survivors: v > th -> cand; v == th -> eqbuf ----
    if (tid == 0) s_eqc = 0;
    __syncthreads();
    if (usec) {
        for (int l = tid; l < ncb; l += 1024) {
            unsigned long long kv = cbuf[l];
            unsigned v = (unsigned)(kv >> 32);
            if (v > th) {
                unsigned p = atomicAdd(&s_cnt, 1u);
                cand[p] = kv;
            } else if (v == th) {
                unsigned p = atomicAdd(&s_eqc, 1u);
                if (p < 2048u) eqbuf[p] = (int)(~(unsigned)(kv & 0xffffffffu));
            }
        }
    } else {
        for (int i = tid; i < TOKENS; i += 1024) {
            unsigned v = vals[i];
            if (v > th && (v >> 21) == pre11) {
                unsigned p = atomicAdd(&s_cnt, 1u);
                cand[p] = ((unsigned long long)v << 32) | (unsigned)(~(unsigned)i);
            } else if (v == th) {
                unsigned p = atomicAdd(&s_eqc, 1u);
                if (p < 2048u) eqbuf[p] = i;
            }
        }
    }
    __syncthreads();
    const int cnt_eq = (int)s_eqc;
    const int eqbase = CAP - r;

    if (cnt_eq == r) {
        for (int l = tid; l < r; l += 1024)
            cand[eqbase + l] =
                ((unsigned long long)th << 32) | (unsigned)(~(unsigned)eqbuf[l]);
    } else if (cnt_eq <= 2048) {
        for (int l = tid; l < cnt_eq; l += 1024) {
            int idx = eqbuf[l];
            int rank = 0;
            for (int m = 0; m < cnt_eq; m++) rank += (eqbuf[m] < idx) ? 1 : 0;
            if (rank < r)
                cand[eqbase + rank] =
                    ((unsigned long long)th << 32) | (unsigned)(~(unsigned)idx);
        }
    } else {
        for (int i = tid; i < TOKENS; i += 1024) {
            if (vals[i] == th) {
                int rank = 0;
                for (int j = 0; j < i; j++) rank += (vals[j] == th) ? 1 : 0;
                if (rank < r)
                    cand[eqbase + rank] =
                        ((unsigned long long)th << 32) | (unsigned)(~(unsigned)i);
            }
        }
    }
    __syncthreads();

    // ---- hybrid bitonic sort: 1024 keys, DESC (val desc, idx asc) ----
    unsigned long long key = cand[tid];
#pragma unroll 1
    for (unsigned kk = 2; kk <= 1024; kk <<= 1) {
        unsigned j = kk >> 1;
        for (; j >= 32; j >>= 1) {
            cand[tid] = key;
            __syncthreads();
            unsigned long long p = cand[tid ^ j];
            bool up = ((tid & kk) == 0);
            bool lowr = ((tid & j) == 0);
            bool takeMax = (up == lowr);
            key = takeMax ? (key > p ? key : p) : (key > p ? p : key);
            __syncthreads();
        }
        for (; j >= 1; j >>= 1) {
            unsigned long long p = __shfl_xor_sync(0xffffffffu, key, j);
            bool up = ((tid & kk) == 0);
            bool lowr = ((tid & j) == 0);
            bool takeMax = (up == lowr);
            key = takeMax ? (key > p ? key : p) : (key > p ? p : key);
        }
    }

    unsigned m   = (unsigned)(key >> 32);
    unsigned idx = ~(unsigned)(key & 0xffffffffu);
    out_val[(size_t)e * CAP + tid] = mono_inv(m);
    out_idx[(size_t)e * CAP + tid] = (float)idx;
}

// ---------------- probs = fl( expf(l - M) / S ), vectorized x4 ------------
__global__ __launch_bounds__(256) void probs_kernel(
    const float* __restrict__ logits, float* __restrict__ probs)
{
    __shared__ float sM[64], sS[64];
    if (threadIdx.x < 64) {
        sM[threadIdx.x] = g_gmax[threadIdx.x];
        sS[threadIdx.x] = g_sum[threadIdx.x];
    }
    __syncthreads();
    int i4 = (blockIdx.x * 256 + threadIdx.x) * 4;
    float4 l = *(const float4*)(logits + i4);
    int e0 = i4 & 63;
    float4 p;
    p.x = __fdiv_rn(expf(__fsub_rn(l.x, sM[e0 + 0])), sS[e0 + 0]);
    p.y = __fdiv_rn(expf(__fsub_rn(l.y, sM[e0 + 1])), sS[e0 + 1]);
    p.z = __fdiv_rn(expf(__fsub_rn(l.z, sM[e0 + 2])), sS[e0 + 2]);
    p.w = __fdiv_rn(expf(__fsub_rn(l.w, sM[e0 + 3])), sS[e0 + 3]);
    *(float4*)(probs + i4) = p;
}

// ---------------- launch ----------------
extern "C" void kernel_launch(void* const* d_in, const int* in_sizes, int n_in,
                              void* d_out, int out_size)
{
    const float* x = (const float*)d_in[0];
    const float* W = (const float*)d_in[1];
    const float* b = (const float*)d_in[2];
    (void)in_sizes; (void)n_in; (void)out_size;

    float* out    = (float*)d_out;
    float* logits = out;                                  // 32768*64
    float* probs  = out + (size_t)TOKENS * NEXP;          // 32768*64
    float* ep     = out + 2 * (size_t)TOKENS * NEXP;      // 64*1024
    float* ei     = ep  + (size_t)NEXP * CAP;             // 64*1024

    cudaFuncSetAttribute(gemm_split2_kernel,
                         cudaFuncAttributeMaxDynamicSharedMemorySize, GEMM_SMEM);
    cudaFuncSetAttribute(topk_kernel,
                         cudaFuncAttributeMaxDynamicSharedMemorySize, TOPK_SMEM);

    gemm_split2_kernel<<<GEMM_BLOCKS, 256, GEMM_SMEM>>>(x, W, b, logits);
    max_kernel<<<NEXP, 256>>>();
    sumexp_kernel<<<256, 256>>>();
    sumred_kernel<<<NEXP, 1024>>>();
    keys_kernel<<<512, 256>>>();
    topk_kernel<<<NEXP, 1024, TOPK_SMEM>>>(ep, ei);
    probs_kernel<<<(TOKENS * NEXP) / 1024, 256>>>(logits, probs);
}

// round 17
// speedup vs baseline: 1.1318x; 1.0226x over previous
#include <cuda_runtime.h>
#include <cstdint>
#include <math.h>

#define TOKENS 32768
#define DMODEL 1024
#define NEXP   64
#define CAP    1024
#define GEMM_BLOCKS 256   /* 32768 / 128 */

// ---------------- scratch (device globals, no allocation) ----------------
__device__ float g_pmax[GEMM_BLOCKS * NEXP];
__device__ float g_gmax[NEXP];
__device__ float g_sum[NEXP];
__device__ float g_lT[(size_t)NEXP * TOKENS];      // logits transposed [e][t]
__device__ double g_dred[NEXP * 1024];             // per-(e,vthread) f64 partials
__device__ unsigned g_kT[(size_t)NEXP * TOKENS];   // u values then keys [e][t]

__device__ __forceinline__ void cp_async16(void* sdst, const void* gsrc) {
    unsigned s = (unsigned)__cvta_generic_to_shared(sdst);
    asm volatile("cp.async.cg.shared.global [%0], [%1], 16;" :: "r"(s), "l"(gsrc));
}

// ---------------- GEMM: logits = x @ W + b, 2-way block-split-K ----------
// Bitwise contract (== reference, verified R7..R16): per output,
//   acc_lo = ascending-k FMA chain over k in [0,512)
//   acc_hi = ascending-k FMA chain over k in [512,1024)
//   logit  = fl(fl(acc_lo + acc_hi) + bias)
// R12/R14 kernel verbatim (measured 104.2-104.8 us).
#define AS_PAD 36
#define GEMM_SMEM ((2 * 128 * AS_PAD + 2 * 2048 + 1024) * 4)   /* 57344 B */

__global__ __launch_bounds__(256, 2) void gemm_split2_kernel(
    const float* __restrict__ x, const float* __restrict__ W,
    const float* __restrict__ bias_in, float* __restrict__ logits)
{
    extern __shared__ float sm_f[];
    float* Asm = sm_f;
    float* Bsm = sm_f + 2 * 128 * AS_PAD;
    float* red = Bsm + 2 * 2048;

    const int tid = threadIdx.x;
    const int tx = tid & 15;
    const int ty = tid >> 4;
    const int m_base = blockIdx.x * 128;
    const float* xblk = x + (size_t)m_base * DMODEL;

    const int am0 = tid >> 3, ac0 = tid & 7;
    const int bk0 = tid >> 4, bn0 = tid & 15;

    float acc[8][4];
    float accL[8][4];
#pragma unroll
    for (int i = 0; i < 8; i++)
#pragma unroll
        for (int j = 0; j < 4; j++) acc[i][j] = 0.0f;

    {
        float* Ab = Asm; float* Bb = Bsm;
#pragma unroll
        for (int j = 0; j < 4; j++) {
            int m = am0 + j * 32;
            cp_async16(&Ab[m * AS_PAD + ac0 * 4],
                       xblk + (size_t)m * DMODEL + ac0 * 4);
        }
#pragma unroll
        for (int j = 0; j < 2; j++) {
            int kk = bk0 + j * 16;
            cp_async16(&Bb[kk * 64 + bn0 * 4],
                       W + (size_t)kk * NEXP + bn0 * 4);
        }
        asm volatile("cp.async.commit_group;");
    }

#pragma unroll 1
    for (int i = 0; i < 32; i++) {
        if (i < 31) {
            const int kc = (i + 1) * 32;
            float* Ab = Asm + ((i + 1) & 1) * (128 * AS_PAD);
            float* Bb = Bsm + ((i + 1) & 1) * 2048;
#pragma unroll
            for (int j = 0; j < 4; j++) {
                int m = am0 + j * 32;
                cp_async16(&Ab[m * AS_PAD + ac0 * 4],
                           xblk + (size_t)m * DMODEL + kc + ac0 * 4);
            }
#pragma unroll
            for (int j = 0; j < 2; j++) {
                int kk = bk0 + j * 16;
                cp_async16(&Bb[kk * 64 + bn0 * 4],
                           W + (size_t)(kc + kk) * NEXP + bn0 * 4);
            }
            asm volatile("cp.async.commit_group;");
            asm volatile("cp.async.wait_group 1;" ::: "memory");
        } else {
            asm volatile("cp.async.wait_group 0;" ::: "memory");
        }
        __syncthreads();

        const float* Ab = Asm + (i & 1) * (128 * AS_PAD);
        const float* Bb = Bsm + (i & 1) * 2048;
#pragma unroll
        for (int g = 0; g < 8; g++) {
            float4 b0 = *(const float4*)&Bb[(g * 4 + 0) * 64 + tx * 4];
            float4 b1 = *(const float4*)&Bb[(g * 4 + 1) * 64 + tx * 4];
            float4 b2 = *(const float4*)&Bb[(g * 4 + 2) * 64 + tx * 4];
            float4 b3 = *(const float4*)&Bb[(g * 4 + 3) * 64 + tx * 4];
#pragma unroll
            for (int ii = 0; ii < 8; ii++) {
                float4 a = *(const float4*)&Ab[(ty * 8 + ii) * AS_PAD + g * 4];
                acc[ii][0] = __fmaf_rn(a.x, b0.x, acc[ii][0]);
                acc[ii][1] = __fmaf_rn(a.x, b0.y, acc[ii][1]);
                acc[ii][2] = __fmaf_rn(a.x, b0.z, acc[ii][2]);
                acc[ii][3] = __fmaf_rn(a.x, b0.w, acc[ii][3]);
                acc[ii][0] = __fmaf_rn(a.y, b1.x, acc[ii][0]);
                acc[ii][1] = __fmaf_rn(a.y, b1.y, acc[ii][1]);
                acc[ii][2] = __fmaf_rn(a.y, b1.z, acc[ii][2]);
                acc[ii][3] = __fmaf_rn(a.y, b1.w, acc[ii][3]);
                acc[ii][0] = __fmaf_rn(a.z, b2.x, acc[ii][0]);
                acc[ii][1] = __fmaf_rn(a.z, b2.y, acc[ii][1]);
                acc[ii][2] = __fmaf_rn(a.z, b2.z, acc[ii][2]);
                acc[ii][3] = __fmaf_rn(a.z, b2.w, acc[ii][3]);
                acc[ii][0] = __fmaf_rn(a.w, b3.x, acc[ii][0]);
                acc[ii][1] = __fmaf_rn(a.w, b3.y, acc[ii][1]);
                acc[ii][2] = __fmaf_rn(a.w, b3.z, acc[ii][2]);
                acc[ii][3] = __fmaf_rn(a.w, b3.w, acc[ii][3]);
            }
        }
        __syncthreads();

        if (i == 15) {
#pragma unroll
            for (int ii = 0; ii < 8; ii++)
#pragma unroll
                for (int j = 0; j < 4; j++) { accL[ii][j] = acc[ii][j]; acc[ii][j] = 0.0f; }
        }
    }

    float4 bb = *(const float4*)(bias_in + tx * 4);
    float bias[4] = {bb.x, bb.y, bb.z, bb.w};
    float fin[8][4];
#pragma unroll
    for (int i = 0; i < 8; i++)
#pragma unroll
        for (int j = 0; j < 4; j++)
            fin[i][j] = __fadd_rn(__fadd_rn(accL[i][j], acc[i][j]), bias[j]);

    float cmax[4] = {-3.4e38f, -3.4e38f, -3.4e38f, -3.4e38f};
#pragma unroll
    for (int i = 0; i < 8; i++) {
        float4 o = make_float4(fin[i][0], fin[i][1], fin[i][2], fin[i][3]);
        *(float4*)(logits + (size_t)(m_base + ty * 8 + i) * NEXP + tx * 4) = o;
        cmax[0] = fmaxf(cmax[0], o.x); cmax[1] = fmaxf(cmax[1], o.y);
        cmax[2] = fmaxf(cmax[2], o.z); cmax[3] = fmaxf(cmax[3], o.w);
    }
#pragma unroll
    for (int j = 0; j < 4; j++) {
        float4 t0 = make_float4(fin[0][j], fin[1][j], fin[2][j], fin[3][j]);
        float4 t1 = make_float4(fin[4][j], fin[5][j], fin[6][j], fin[7][j]);
        float* base = g_lT + (size_t)(tx * 4 + j) * TOKENS + m_base + ty * 8;
        *(float4*)(base + 0) = t0;
        *(float4*)(base + 4) = t1;
    }
#pragma unroll
    for (int j = 0; j < 4; j++) red[ty * 64 + tx * 4 + j] = cmax[j];
    __syncthreads();
    if (tid < 64) {
        float m = red[tid];
#pragma unroll
        for (int w = 1; w < 16; w++) m = fmaxf(m, red[w * 64 + tid]);
        g_pmax[(size_t)blockIdx.x * NEXP + tid] = m;
    }
}

// ---------------- stats: fused M + expf + u store + f64 partials ----------
// Block b handles expert e = b>>2, vthreads vt = (b&3)*256 + tid.
// M: fmax tree over 256 per-tile maxes (order-free exact, == max_kernel).
// Partial: EXACT old per-vthread loop; u values stored to g_kT (as float).
__global__ __launch_bounds__(256) void stats_kernel()
{
    __shared__ float fred[256];
    const int tid = threadIdx.x;
    const int b   = blockIdx.x;          // 0..255
    const int e   = b >> 2;
    const int vt  = (b & 3) * 256 + tid; // 0..1023

    fred[tid] = g_pmax[(size_t)tid * NEXP + e];
    __syncthreads();
    for (int st = 128; st > 0; st >>= 1) {
        if (tid < st) fred[tid] = fmaxf(fred[tid], fred[tid + st]);
        __syncthreads();
    }
    const float M = fred[0];
    if ((b & 3) == 0 && tid == 0) g_gmax[e] = M;

    const float4* colL = (const float4*)(g_lT + (size_t)e * TOKENS);
    float4*       colU = (float4*)(g_kT + (size_t)e * TOKENS);

    double s0 = 0.0, s1 = 0.0, s2 = 0.0, s3 = 0.0;
#pragma unroll
    for (int i = vt; i < TOKENS / 4; i += 1024) {
        float4 l = colL[i];
        float u0 = expf(__fsub_rn(l.x, M));
        float u1 = expf(__fsub_rn(l.y, M));
        float u2 = expf(__fsub_rn(l.z, M));
        float u3 = expf(__fsub_rn(l.w, M));
        colU[i] = make_float4(u0, u1, u2, u3);
        s0 += (double)u0; s1 += (double)u1; s2 += (double)u2; s3 += (double)u3;
    }
    g_dred[e * 1024 + vt] = (s0 + s1) + (s2 + s3);
}

// ---------------- keys: fused exact S-tree + key conversion in place ------
__device__ __forceinline__ unsigned mono_fwd(float f) {
    unsigned u = __float_as_uint(f);
    return (u & 0x80000000u) ? ~u : (u | 0x80000000u);
}
__device__ __forceinline__ float mono_inv(unsigned m) {
    unsigned u = (m & 0x80000000u) ? (m ^ 0x80000000u) : ~m;
    return __uint_as_float(u);
}

// Block b: expert e = b>>3, slice part = b&7 (1024 float4 each).
// S: replay the EXACT 1024-slot pairwise tree (levels barrier-separated;
// thread mapping within a level is irrelevant to the result bits).
__global__ __launch_bounds__(256) void keys_kernel()
{
    __shared__ double dred[1024];
    const int tid = threadIdx.x;
    const int b   = blockIdx.x;          // 0..511
    const int e   = b >> 3;
    const int part = b & 7;

    const double* src = g_dred + e * 1024;
    dred[tid]       = src[tid];
    dred[tid + 256] = src[tid + 256];
    dred[tid + 512] = src[tid + 512];
    dred[tid + 768] = src[tid + 768];
    __syncthreads();
    // level st=512: 512 adds, 2 per thread
    dred[tid]       += dred[tid + 512];
    dred[tid + 256] += dred[tid + 256 + 512];
    __syncthreads();
    // level st=256
    dred[tid] += dred[tid + 256];
    __syncthreads();
    for (int st = 128; st > 0; st >>= 1) {
        if (tid < st) dred[tid] += dred[tid + st];
        __syncthreads();
    }
    const float S = (float)dred[0];
    if (part == 0 && tid == 0) g_sum[e] = S;

    float4* colU = (float4*)(g_kT + (size_t)e * TOKENS);
    uint4*  colK = (uint4*)(g_kT + (size_t)e * TOKENS);
    const int base = part * 1024;
#pragma unroll
    for (int j = 0; j < 4; j++) {
        int i = base + j * 256 + tid;
        float4 u = colU[i];
        uint4 k;
        k.x = mono_fwd(__fdiv_rn(u.x, S));
        k.y = mono_fwd(__fdiv_rn(u.y, S));
        k.z = mono_fwd(__fdiv_rn(u.z, S));
        k.w = mono_fwd(__fdiv_rn(u.w, S));
        colK[i] = k;
    }
}

// ---------------- topk: select + sort only (== R16) -----------------------
#define OFF_VALS  0
#define OFF_CAND  131072
#define OFF_HIST  (131072 + 8192)
#define OFF_WTMP  (131072 + 16384)
#define OFF_CBUF  (131072 + 16384 + 128)
#define CBUF_N    8192
#define TOPK_SMEM (OFF_CBUF + CBUF_N * 8)

__device__ __forceinline__ void block_select2048(
    unsigned* hist, unsigned* wtmp, int k, int tid,
    volatile int* s_sel, volatile int* s_rem)
{
    const int lane = tid & 31, wid = tid >> 5;
    unsigned a = hist[2047 - 2 * tid];
    unsigned b = hist[2047 - (2 * tid + 1)];
    unsigned s = a + b, v = s;
#pragma unroll
    for (int o = 1; o < 32; o <<= 1) {
        unsigned n = __shfl_up_sync(0xffffffffu, v, o);
        if (lane >= o) v += n;
    }
    if (lane == 31) wtmp[wid] = v;
    __syncthreads();
    if (wid == 0) {
        unsigned w = wtmp[lane], vv = w;
#pragma unroll
        for (int o = 1; o < 32; o <<= 1) {
            unsigned n = __shfl_up_sync(0xffffffffu, vv, o);
            if (lane >= o) vv += n;
        }
        wtmp[lane] = vv - w;
    }
    __syncthreads();
    unsigned ex = wtmp[wid] + (v - s);
    unsigned uk = (unsigned)k;
    if (ex < uk && uk <= ex + a) { *s_sel = 2047 - 2 * tid; *s_rem = (int)(uk - ex); }
    unsigned e1 = ex + a;
    if (e1 < uk && uk <= e1 + b) { *s_sel = 2046 - 2 * tid; *s_rem = (int)(uk - e1); }
    __syncthreads();
}

__global__ __launch_bounds__(1024) void topk_kernel(
    float* __restrict__ out_val, float* __restrict__ out_idx)
{
    extern __shared__ unsigned char sm_raw[];
    unsigned*           vals = (unsigned*)(sm_raw + OFF_VALS);
    unsigned long long* cand = (unsigned long long*)(sm_raw + OFF_CAND);
    unsigned*           hist = (unsigned*)(sm_raw + OFF_HIST);
    int*                eqbuf = (int*)(sm_raw + OFF_HIST);
    unsigned*           wtmp = (unsigned*)(sm_raw + OFF_WTMP);
    unsigned long long* cbuf = (unsigned long long*)(sm_raw + OFF_CBUF);

    __shared__ volatile int s_sel;
    __shared__ volatile int s_k;
    __shared__ unsigned     s_cnt;
    __shared__ unsigned     s_eqc;
    __shared__ unsigned     s_cb;

    const int tid = threadIdx.x;
    const int e   = blockIdx.x;

    hist[tid] = 0; hist[tid + 1024] = 0;
    __syncthreads();
    const uint4* colk = (const uint4*)(g_kT + (size_t)e * TOKENS);
    for (int i = tid; i < TOKENS / 4; i += 1024) {
        uint4 kv = colk[i];
        ((uint4*)vals)[i] = kv;
        atomicAdd(&hist[kv.x >> 21], 1u);
        atomicAdd(&hist[kv.y >> 21], 1u);
        atomicAdd(&hist[kv.z >> 21], 1u);
        atomicAdd(&hist[kv.w >> 21], 1u);
    }
    __syncthreads();

    block_select2048(hist, wtmp, CAP, tid, &s_sel, &s_k);
    const unsigned pre11 = (unsigned)s_sel;
    int krem = s_k;
    __syncthreads();

    if (tid == 0) { s_cnt = 0; s_cb = 0; }
    __syncthreads();
    for (int i = tid; i < TOKENS; i += 1024) {
        unsigned v = vals[i];
        unsigned bin = v >> 21;
        if (bin > pre11) {
            unsigned p = atomicAdd(&s_cnt, 1u);
            cand[p] = ((unsigned long long)v << 32) | (unsigned)(~(unsigned)i);
        } else if (bin == pre11) {
            unsigned p = atomicAdd(&s_cb, 1u);
            if (p < CBUF_N) cbuf[p] = ((unsigned long long)v << 32)
                                      | (unsigned)(~(unsigned)i);
        }
    }
    __syncthreads();
    const bool usec = (s_cb <= CBUF_N);
    const int  ncb  = usec ? (int)s_cb : 0;

    hist[tid] = 0; hist[tid + 1024] = 0;
    __syncthreads();
    if (usec) {
        for (int l = tid; l < ncb; l += 1024)
            atomicAdd(&hist[((unsigned)(cbuf[l] >> 42)) & 0x7FFu], 1u);
    } else {
        for (int i = tid; i < TOKENS; i += 1024) {
            unsigned v = vals[i];
            if ((v >> 21) == pre11) atomicAdd(&hist[(v >> 10) & 0x7FFu], 1u);
        }
    }
    __syncthreads();
    block_select2048(hist, wtmp, krem, tid, &s_sel, &s_k);
    const unsigned pre22 = (pre11 << 11) | (unsigned)s_sel;
    krem = s_k;
    __syncthreads();

    hist[tid] = 0; hist[tid + 1024] = 0;
    __syncthreads();
    if (usec) {
        for (int l = tid; l < ncb; l += 1024) {
            unsigned v = (unsigned)(cbuf[l] >> 32);
            if ((v >> 10) == pre22) atomicAdd(&hist[v & 0x3FFu], 1u);
        }
    } else {
        for (int i = tid; i < TOKENS; i += 1024) {
            unsigned v = vals[i];
            if ((v >> 10) == pre22) atomicAdd(&hist[v & 0x3FFu], 1u);
        }
    }
    __syncthreads();
    block_select2048(hist, wtmp, krem, tid, &s_sel, &s_k);
    const unsigned th = (pre22 << 10) | (unsigned)s_sel;
    const int r = s_k;
    __syncthreads();

    if (tid == 0) s_eqc = 0;
    __syncthreads();
    if (usec) {
        for (int l = tid; l < ncb; l += 1024) {
            unsigned long long kv = cbuf[l];
            unsigned v = (unsigned)(kv >> 32);
            if (v > th) {
                unsigned p = atomicAdd(&s_cnt, 1u);
                cand[p] = kv;
            } else if (v == th) {
                unsigned p = atomicAdd(&s_eqc, 1u);
                if (p < 2048u) eqbuf[p] = (int)(~(unsigned)(kv & 0xffffffffu));
            }
        }
    } else {
        for (int i = tid; i < TOKENS; i += 1024) {
            unsigned v = vals[i];
            if (v > th && (v >> 21) == pre11) {
                unsigned p = atomicAdd(&s_cnt, 1u);
                cand[p] = ((unsigned long long)v << 32) | (unsigned)(~(unsigned)i);
            } else if (v == th) {
                unsigned p = atomicAdd(&s_eqc, 1u);
                if (p < 2048u) eqbuf[p] = i;
            }
        }
    }
    __syncthreads();
    const int cnt_eq = (int)s_eqc;
    const int eqbase = CAP - r;

    if (cnt_eq == r) {
        for (int l = tid; l < r; l += 1024)
            cand[eqbase + l] =
                ((unsigned long long)th << 32) | (unsigned)(~(unsigned)eqbuf[l]);
    } else if (cnt_eq <= 2048) {
        for (int l = tid; l < cnt_eq; l += 1024) {
            int idx = eqbuf[l];
            int rank = 0;
            for (int m = 0; m < cnt_eq; m++) rank += (eqbuf[m] < idx) ? 1 : 0;
            if (rank < r)
                cand[eqbase + rank] =
                    ((unsigned long long)th << 32) | (unsigned)(~(unsigned)idx);
        }
    } else {
        for (int i = tid; i < TOKENS; i += 1024) {
            if (vals[i] == th) {
                int rank = 0;
                for (int j = 0; j < i; j++) rank += (vals[j] == th) ? 1 : 0;
                if (rank < r)
                    cand[eqbase + rank] =
                        ((unsigned long long)th << 32) | (unsigned)(~(unsigned)i);
            }
        }
    }
    __syncthreads();

    unsigned long long key = cand[tid];
#pragma unroll 1
    for (unsigned kk = 2; kk <= 1024; kk <<= 1) {
        unsigned j = kk >> 1;
        for (; j >= 32; j >>= 1) {
            cand[tid] = key;
            __syncthreads();
            unsigned long long p = cand[tid ^ j];
            bool up = ((tid & kk) == 0);
            bool lowr = ((tid & j) == 0);
            bool takeMax = (up == lowr);
            key = takeMax ? (key > p ? key : p) : (key > p ? p : key);
            __syncthreads();
        }
        for (; j >= 1; j >>= 1) {
            unsigned long long p = __shfl_xor_sync(0xffffffffu, key, j);
            bool up = ((tid & kk) == 0);
            bool lowr = ((tid & j) == 0);
            bool takeMax = (up == lowr);
            key = takeMax ? (key > p ? key : p) : (key > p ? p : key);
        }
    }

    unsigned m   = (unsigned)(key >> 32);
    unsigned idx = ~(unsigned)(key & 0xffffffffu);
    out_val[(size_t)e * CAP + tid] = mono_inv(m);
    out_idx[(size_t)e * CAP + tid] = (float)idx;
}

// ---------------- probs = fl( expf(l - M) / S ), vectorized x4 ------------
__global__ __launch_bounds__(256) void probs_kernel(
    const float* __restrict__ logits, float* __restrict__ probs)
{
    __shared__ float sM[64], sS[64];
    if (threadIdx.x < 64) {
        sM[threadIdx.x] = g_gmax[threadIdx.x];
        sS[threadIdx.x] = g_sum[threadIdx.x];
    }
    __syncthreads();
    int i4 = (blockIdx.x * 256 + threadIdx.x) * 4;
    float4 l = *(const float4*)(logits + i4);
    int e0 = i4 & 63;
    float4 p;
    p.x = __fdiv_rn(expf(__fsub_rn(l.x, sM[e0 + 0])), sS[e0 + 0]);
    p.y = __fdiv_rn(expf(__fsub_rn(l.y, sM[e0 + 1])), sS[e0 + 1]);
    p.z = __fdiv_rn(expf(__fsub_rn(l.z, sM[e0 + 2])), sS[e0 + 2]);
    p.w = __fdiv_rn(expf(__fsub_rn(l.w, sM[e0 + 3])), sS[e0 + 3]);
    *(float4*)(probs + i4) = p;
}

// ---------------- launch ----------------
extern "C" void kernel_launch(void* const* d_in, const int* in_sizes, int n_in,
                              void* d_out, int out_size)
{
    const float* x = (const float*)d_in[0];
    const float* W = (const float*)d_in[1];
    const float* b = (const float*)d_in[2];
    (void)in_sizes; (void)n_in; (void)out_size;

    float* out    = (float*)d_out;
    float* logits = out;                                  // 32768*64
    float* probs  = out + (size_t)TOKENS * NEXP;          // 32768*64
    float* ep     = out + 2 * (size_t)TOKENS * NEXP;      // 64*1024
    float* ei     = ep  + (size_t)NEXP * CAP;             // 64*1024

    cudaFuncSetAttribute(gemm_split2_kernel,
                         cudaFuncAttributeMaxDynamicSharedMemorySize, GEMM_SMEM);
    cudaFuncSetAttribute(topk_kernel,
                         cudaFuncAttributeMaxDynamicSharedMemorySize, TOPK_SMEM);

    gemm_split2_kernel<<<GEMM_BLOCKS, 256, GEMM_SMEM>>>(x, W, b, logits);
    stats_kernel<<<256, 256>>>();
    keys_kernel<<<512, 256>>>();
    topk_kernel<<<NEXP, 1024, TOPK_SMEM>>>(ep, ei);
    probs_kernel<<<(TOKENS * NEXP) / 1024, 256>>>(logits, probs);
}